// round 17
// baseline (speedup 1.0000x reference)
#include <cuda_runtime.h>
#include <cstdint>

// ---------------- Problem dims ----------------
#define B_DIM   64
#define T_DIM   500
#define IN_DIM  512
#define HID_DIM 2048
#define OUT_DIM 128
#define M_DIM   (B_DIM * T_DIM)          // 32000

// LIF constants
#define A_S1 0.81873075307798182f
#define SC1  0.90634623461009088f
#define A_M1 0.90483741803595952f
#define BM1  0.09516258196404048f
#define TH1  0.5f
#define A_S2 0.90483741803595952f
#define SC2  0.95162581964040482f
#define A_M2 0.95122942450071402f
#define BM2  0.04877057549928598f
#define TH2  1.0f

// ---------------- Scratch (device globals) ----------------
__device__ float    g_c1[(size_t)M_DIM * HID_DIM];   // 262 MB: X @ W1
__device__ float    g_c2[(size_t)M_DIM * OUT_DIM];   // 16.4 MB: spk1 @ W2
__device__ uint32_t g_bm[(size_t)M_DIM * 64];        // 8.2 MB spike bitmask

// ---------------- helpers ----------------
__device__ __forceinline__ uint32_t smem_u32(const void* p) {
    uint32_t a;
    asm("{ .reg .u64 t; cvta.to.shared.u64 t, %1; cvt.u32.u64 %0, t; }" : "=r"(a) : "l"(p));
    return a;
}
__device__ __forceinline__ void cp16(uint32_t d, const void* g) {
    asm volatile("cp.async.cg.shared.global [%0], [%1], 16;" :: "r"(d), "l"(g));
}
#define CP_COMMIT() asm volatile("cp.async.commit_group;" ::: "memory")
#define CP_WAIT0()  asm volatile("cp.async.wait_group 0;" ::: "memory")

// ---------------- SGEMM1: 256x128 tile, 16x8 microtile, double-buffered ----------
// C[M x N] = A[M x K] @ B[K x N]. 256 threads; thread (ty,tx)=(tid>>4, tid&15)
// owns rows {64g + 4ty + i : g=0..3, i=0..3} x cols {4tx..+3, 64+4tx..+3}.
// Per k: 4 LDS.128 A-broadcasts + 2 conflict-free LDS.128 B = 6 LDS / 128 FMA.
// B via cp.async, A via LDG->reg->STS prefetched 2 tiles ahead, 1 sync/tile.
// Ascending-k chain per element -> bit-identical to R1 baseline.
#define GBM 256
#define GBN 128
#define GBK 16
#define APAD 260
#define NKT (IN_DIM / GBK)                // 32 K-tiles

__global__ __launch_bounds__(256, 1)
void sgemm1_kernel(const float* __restrict__ A, const float* __restrict__ B,
                   float* __restrict__ C) {
    __shared__ float As[2][GBK][APAD];    // 33.3 KB
    __shared__ float Bs[2][GBK][GBN];     // 16 KB

    const int tid  = threadIdx.x;
    const int ty   = tid >> 4;            // 0..15
    const int tx   = tid & 15;            // 0..15
    const int brow = blockIdx.y * GBM;
    const int bcol = blockIdx.x * GBN;

    const int arow = tid >> 2;            // 0..63 (+64i)
    const int akc  = (tid & 3) << 2;
    const int brw  = tid >> 5;            // 0..7
    const int bc4  = (tid & 31) << 2;

    float4 areg[4];

    auto ldgA = [&](int c) {
        #pragma unroll
        for (int i = 0; i < 4; i++)
            areg[i] = *reinterpret_cast<const float4*>(
                &A[(size_t)(brow + arow + 64 * i) * IN_DIM + c * GBK + akc]);
    };
    auto stsA = [&](int st) {
        #pragma unroll
        for (int i = 0; i < 4; i++) {
            As[st][akc + 0][arow + 64 * i] = areg[i].x;
            As[st][akc + 1][arow + 64 * i] = areg[i].y;
            As[st][akc + 2][arow + 64 * i] = areg[i].z;
            As[st][akc + 3][arow + 64 * i] = areg[i].w;
        }
    };
    auto cpB = [&](int c, int st) {
        cp16(smem_u32(&Bs[st][brw][bc4]),
             &B[(size_t)(c * GBK + brw) * HID_DIM + bcol + bc4]);
        cp16(smem_u32(&Bs[st][8 + brw][bc4]),
             &B[(size_t)(c * GBK + 8 + brw) * HID_DIM + bcol + bc4]);
    };

    float acc[16][8] = {};                // [4g+i][col half*4 + j]

    // prologue
    ldgA(0);
    cpB(0, 0); CP_COMMIT();
    stsA(0);
    ldgA(1);

    for (int i = 0; i < NKT; i++) {
        const int st = i & 1;
        CP_WAIT0();
        __syncthreads();
        if (i + 1 < NKT) {
            cpB(i + 1, st ^ 1); CP_COMMIT();
            stsA(st ^ 1);
        }
        if (i + 2 < NKT) ldgA(i + 2);

        #pragma unroll
        for (int k = 0; k < GBK; k++) {
            float ar[16], br[8];
            #pragma unroll
            for (int g = 0; g < 4; g++) {
                float4 a = *reinterpret_cast<const float4*>(&As[st][k][64 * g + 4 * ty]);
                ar[4 * g + 0] = a.x; ar[4 * g + 1] = a.y;
                ar[4 * g + 2] = a.z; ar[4 * g + 3] = a.w;
            }
            float4 b0 = *reinterpret_cast<const float4*>(&Bs[st][k][4 * tx]);
            float4 b1 = *reinterpret_cast<const float4*>(&Bs[st][k][64 + 4 * tx]);
            br[0] = b0.x; br[1] = b0.y; br[2] = b0.z; br[3] = b0.w;
            br[4] = b1.x; br[5] = b1.y; br[6] = b1.z; br[7] = b1.w;
            #pragma unroll
            for (int u = 0; u < 16; u++)
                #pragma unroll
                for (int v = 0; v < 8; v++)
                    acc[u][v] = fmaf(ar[u], br[v], acc[u][v]);
        }
    }

    // Store: rows 64g + 4ty + i, col halves {4tx, 64+4tx}
    #pragma unroll
    for (int g = 0; g < 4; g++)
        #pragma unroll
        for (int i = 0; i < 4; i++) {
            float* rp = &C[(size_t)(brow + 64 * g + 4 * ty + i) * HID_DIM + bcol];
            *reinterpret_cast<float4*>(rp + 4 * tx) =
                make_float4(acc[4 * g + i][0], acc[4 * g + i][1],
                            acc[4 * g + i][2], acc[4 * g + i][3]);
            *reinterpret_cast<float4*>(rp + 64 + 4 * tx) =
                make_float4(acc[4 * g + i][4], acc[4 * g + i][5],
                            acc[4 * g + i][6], acc[4 * g + i][7]);
        }
}

// ---------------- Layer-1 LIF scan (+ spike bitmask via ballot) ----------------
__global__ __launch_bounds__(256)
void scan1_kernel(const float* __restrict__ c1, float* __restrict__ spk1,
                  float* __restrict__ mems1, uint32_t* __restrict__ bm) {
    int idx = blockIdx.x * blockDim.x + threadIdx.x;
    if (idx >= B_DIM * HID_DIM) return;
    int b = idx >> 11;
    int h = idx & (HID_DIM - 1);
    int lane = threadIdx.x & 31;
    int hw = h >> 5;
    size_t base = (size_t)b * T_DIM * HID_DIM + h;
    float syn = 0.f, mem = 0.f;
    for (int t = 0; t < T_DIM; t++) {
        size_t o = base + (size_t)t * HID_DIM;
        syn = A_S1 * syn + SC1 * c1[o];
        mem = A_M1 * mem + BM1 * syn;
        float s = (mem - TH1 > 0.f) ? 1.f : 0.f;
        mem -= s * TH1;
        spk1[o]  = s;
        mems1[o] = mem;
        uint32_t w = __ballot_sync(0xffffffffu, s > 0.f);
        if (lane == 0) bm[((size_t)b * T_DIM + t) * 64 + hw] = w;
    }
}

// ---------------- Sparse-exact GEMM2 (bit-identical; from R10) ----------------
#define SGK 64
__global__ __launch_bounds__(256, 2)
void spmm2_kernel(const uint32_t* __restrict__ bm, const float* __restrict__ w2,
                  float* __restrict__ c2) {
    __shared__ float ws[SGK][OUT_DIM];

    const int tid  = threadIdx.x;
    const int wid  = tid >> 5;
    const int lane = tid & 31;
    const int rbase = blockIdx.x * 128 + wid * 16;

    float acc[16][4] = {};

    for (int kt = 0; kt < HID_DIM / SGK; kt++) {
        __syncthreads();
        #pragma unroll
        for (int i = 0; i < 8; i++) {
            int s  = tid + i * 256;
            int kk = s >> 5;
            int c4 = (s & 31) * 4;
            *reinterpret_cast<float4*>(&ws[kk][c4]) =
                *reinterpret_cast<const float4*>(
                    &w2[(size_t)(kt * SGK + kk) * OUT_DIM + c4]);
        }
        __syncthreads();

        #pragma unroll
        for (int r = 0; r < 16; r++) {
            size_t m = (size_t)(rbase + r);
            uint32_t w0 = bm[m * 64 + kt * 2];
            uint32_t w1 = bm[m * 64 + kt * 2 + 1];
            while (w0) {
                int k = __ffs(w0) - 1; w0 &= w0 - 1;
                acc[r][0] += ws[k][lane];
                acc[r][1] += ws[k][lane + 32];
                acc[r][2] += ws[k][lane + 64];
                acc[r][3] += ws[k][lane + 96];
            }
            while (w1) {
                int k = __ffs(w1) - 1; w1 &= w1 - 1;
                acc[r][0] += ws[32 + k][lane];
                acc[r][1] += ws[32 + k][lane + 32];
                acc[r][2] += ws[32 + k][lane + 64];
                acc[r][3] += ws[32 + k][lane + 96];
            }
        }
    }

    #pragma unroll
    for (int r = 0; r < 16; r++) {
        float* cp = &c2[(size_t)(rbase + r) * OUT_DIM];
        cp[lane]      = acc[r][0];
        cp[lane + 32] = acc[r][1];
        cp[lane + 64] = acc[r][2];
        cp[lane + 96] = acc[r][3];
    }
}

// ---------------- Layer-2 LIF scan + time reduction ----------------
__global__ __launch_bounds__(256)
void scan2_kernel(const float* __restrict__ c2, float* __restrict__ out,
                  float* __restrict__ spk2, float* __restrict__ mems2) {
    int idx = blockIdx.x * blockDim.x + threadIdx.x;
    if (idx >= B_DIM * OUT_DIM) return;
    int b = idx >> 7;
    int o = idx & (OUT_DIM - 1);
    size_t base = (size_t)b * T_DIM * OUT_DIM + o;
    float syn = 0.f, mem = 0.f, acc = 0.f;
    for (int t = 0; t < T_DIM; t++) {
        size_t off = base + (size_t)t * OUT_DIM;
        syn = A_S2 * syn + SC2 * c2[off];
        mem = A_M2 * mem + BM2 * syn;
        float s = (mem - TH2 > 0.f) ? 1.f : 0.f;
        mem -= s * TH2;
        spk2[off]  = s;
        mems2[off] = mem;
        if (t > 0) acc += mem;
    }
    out[(size_t)b * OUT_DIM + o] = acc / (float)T_DIM;
}

// ---------------- Launch ----------------
extern "C" void kernel_launch(void* const* d_in, const int* in_sizes, int n_in,
                              void* d_out, int out_size) {
    const float* x  = (const float*)d_in[0];   // [B, T, IN]
    const float* w1 = (const float*)d_in[1];   // [IN, HID]
    const float* w2 = (const float*)d_in[2];   // [HID, OUT]

    float* out   = (float*)d_out;
    float* spk1  = out  + (size_t)B_DIM * OUT_DIM;
    float* mems1 = spk1 + (size_t)B_DIM * T_DIM * HID_DIM;
    float* spk2  = mems1 + (size_t)B_DIM * T_DIM * HID_DIM;
    float* mems2 = spk2 + (size_t)B_DIM * T_DIM * OUT_DIM;

    float*    c1; cudaGetSymbolAddress((void**)&c1, g_c1);
    float*    c2; cudaGetSymbolAddress((void**)&c2, g_c2);
    uint32_t* bm; cudaGetSymbolAddress((void**)&bm, g_bm);

    // Stage 1: C1 = X @ W1 (256x128 tile, 16x8 microtile, bit-exact)
    {
        dim3 grid(HID_DIM / GBN, M_DIM / GBM);   // 16 x 125
        sgemm1_kernel<<<grid, 256>>>(x, w1, c1);
    }
    // Stage 2: layer-1 scan -> spk1, mems1, bitmask
    scan1_kernel<<<(B_DIM * HID_DIM) / 256, 256>>>(c1, spk1, mems1, bm);
    // Stage 3: C2 = spk1 @ W2 via sparse-exact bitmask GEMM
    spmm2_kernel<<<M_DIM / 128, 256>>>(bm, w2, c2);
    // Stage 4: layer-2 scan + output reduction
    scan2_kernel<<<(B_DIM * OUT_DIM) / 256, 256>>>(c2, out, spk2, mems2);
}